// round 7
// baseline (speedup 1.0000x reference)
#include <cuda_runtime.h>

#define Bsz 64
#define Tlen 1024
#define CHN 256
#define VOC 32000
#define EMB 64
#define LAT 128

// output layout (floats): O_t, c_t, new_h, new_c (tuple order, flattened)
#define OFF_O  0
#define OFF_CT (Bsz*VOC)
#define OFF_H  (OFF_CT + Bsz*CHN)
#define OFF_C  (OFF_H + Bsz*LAT)

// ---- K1: prev_char @ Wc split-K config ----
#define KC1  160
#define NCH1 (VOC / KC1)      // 200 chunks

// ---- K3: attention T-split ----
#define ACH 8
#define TCH (Tlen / ACH)      // 128

// ---- K4: logits GEMM config (persistent, 64-col chunks) ----
#define KTOT (LAT + CHN)      // 384
#define CCH  64               // cols per chunk
#define NCHK (VOC / CCH)      // 500 chunks
#define GRID4 148             // persistent blocks (1 per SM)

// -------- device scratch (static globals; no allocation) --------
__device__ float g_part1[NCH1 * Bsz * EMB];   // [chunk][b][e]
__device__ float g_Htfm[Bsz * CHN];
__device__ float g_At[KTOT * Bsz];            // A^T[k][b]: rows 0..127 new_h, 128..383 c_t
__device__ float g_as [Bsz * ACH * CHN];
__device__ float g_aws[Bsz * ACH * CHN];
__device__ float g_logits[Bsz * VOC];         // holds exp(logit) after k4a
__device__ float g_psum[GRID4 * Bsz];         // per-(block,b) partial exp sums
__device__ int   g_tick[Bsz];                 // k3 completion tickets (reset by k1)

// -------- f32x2 helpers (sm_103a packed fp32) --------
__device__ __forceinline__ unsigned long long dup2(float x) {
    unsigned long long r;
    asm("mov.b64 %0, {%1, %1};" : "=l"(r) : "f"(x));
    return r;
}
__device__ __forceinline__ void ffma2(unsigned long long& acc,
                                      unsigned long long a,
                                      unsigned long long b) {
    asm("fma.rn.f32x2 %0, %1, %2, %0;" : "+l"(acc) : "l"(a), "l"(b));
}
__device__ __forceinline__ void unpack2(unsigned long long v, float& lo, float& hi) {
    asm("mov.b64 {%0, %1}, %2;" : "=f"(lo), "=f"(hi) : "l"(v));
}
__device__ __forceinline__ float tanhfast(float x) {
    float y; asm("tanh.approx.f32 %0, %1;" : "=f"(y) : "f"(x)); return y;
}

// ================= K1: partials of prev_char[64,32000] @ Wc[32000,64] =================
__global__ void k1_char_gemm(const float* __restrict__ prev_char,
                             const float* __restrict__ Wc) {
    __shared__ float Ws[KC1 * EMB];   // 40 KB
    const int chunk = blockIdx.x;
    const int k0 = chunk * KC1;
    if (threadIdx.x == 0 && chunk < Bsz) g_tick[chunk] = 0;   // reset k3 tickets
    for (int i = threadIdx.x; i < KC1 * EMB; i += 256)
        Ws[i] = Wc[k0 * EMB + i];
    __syncthreads();

    const int eq = threadIdx.x & 15;        // 16 e-groups of 4 cols
    const int bq = threadIdx.x >> 4;        // 16 b-groups of 4 rows
    const int e0 = eq * 4, b0 = bq * 4;
    float acc[4][4] = {};
    const float* a0 = prev_char + (size_t)b0 * VOC + k0;
    #pragma unroll 2
    for (int k = 0; k < KC1; k++) {
        float4 w = *(const float4*)&Ws[k * EMB + e0];
        #pragma unroll
        for (int i = 0; i < 4; i++) {
            float a = __ldg(a0 + (size_t)i * VOC + k);
            acc[i][0] = fmaf(a, w.x, acc[i][0]);
            acc[i][1] = fmaf(a, w.y, acc[i][1]);
            acc[i][2] = fmaf(a, w.z, acc[i][2]);
            acc[i][3] = fmaf(a, w.w, acc[i][3]);
        }
    }
    float* out = g_part1 + (size_t)chunk * Bsz * EMB;
    #pragma unroll
    for (int i = 0; i < 4; i++)
        #pragma unroll
        for (int j = 0; j < 4; j++)
            out[(b0 + i) * EMB + e0 + j] = acc[i][j];
}

// ================= K2: reduce partials + Wct1 term, LSTM cell, H_tfm =================
__global__ void k2_lstm(const float* __restrict__ pcv,
                        const float* __restrict__ state_h,
                        const float* __restrict__ state_c,
                        const float* __restrict__ Wct1,
                        const float* __restrict__ lstm_kernel,
                        const float* __restrict__ lstm_rec,
                        const float* __restrict__ W_h,
                        float* __restrict__ d_out) {
    const int b = blockIdx.x;
    const int tid = threadIdx.x;  // 256
    __shared__ float red_s[4][EMB];
    __shared__ float inp_s[EMB];
    __shared__ float h_s[LAT];
    __shared__ float z_s[4 * LAT];
    __shared__ float nh_s[LAT];

    const int e = tid & 63, g = tid >> 6;
    float acc = 0.f;
    for (int c = g; c < NCH1; c += 4)
        acc += g_part1[((size_t)c * Bsz + b) * EMB + e];
    for (int c = g * 64; c < g * 64 + 64; c++)
        acc = fmaf(pcv[b * CHN + c], Wct1[c * EMB + e], acc);
    red_s[g][e] = acc;
    if (tid < LAT) h_s[tid] = state_h[b * LAT + tid];
    __syncthreads();
    if (tid < EMB)
        inp_s[tid] = red_s[0][tid] + red_s[1][tid] + red_s[2][tid] + red_s[3][tid];
    __syncthreads();

    for (int j = tid; j < 4 * LAT; j += 256) {
        float z = 0.f;
        for (int ee = 0; ee < EMB; ee++)
            z = fmaf(inp_s[ee], lstm_kernel[ee * 4 * LAT + j], z);
        for (int l = 0; l < LAT; l++)
            z = fmaf(h_s[l], lstm_rec[l * 4 * LAT + j], z);
        z_s[j] = z;
    }
    __syncthreads();

    if (tid < LAT) {
        float zi = z_s[tid], zf = z_s[LAT + tid], zg = z_s[2 * LAT + tid], zo = z_s[3 * LAT + tid];
        float i_ = 1.f / (1.f + __expf(-zi));
        float f_ = 1.f / (1.f + __expf(-zf));
        float gg = tanhf(zg);
        float o_ = 1.f / (1.f + __expf(-zo));
        float nc = fmaf(f_, state_c[b * LAT + tid], i_ * gg);
        float nh = o_ * tanhf(nc);
        nh_s[tid] = nh;
        g_At[tid * Bsz + b] = nh;
        d_out[OFF_H + b * LAT + tid] = nh;
        d_out[OFF_C + b * LAT + tid] = fminf(fmaxf(nc, -10.f), 10.f);
    }
    __syncthreads();

    {
        float a2 = 0.f;
        for (int l = 0; l < LAT; l++)
            a2 = fmaf(nh_s[l], W_h[l * CHN + tid], a2);
        g_Htfm[b * CHN + tid] = a2;
    }
}

// ============ K3: attention partials + fused last-block merge -> c_t ============
// no-max softmax is safe: |e_t| <= |V_attn| (tanh bounded)
__global__ void k3_attn(const float* __restrict__ F,
                        const float* __restrict__ V_attn,
                        float* __restrict__ d_out) {
    const int chunk = blockIdx.x, b = blockIdx.y;
    const int ch = threadIdx.x;  // 256
    const float h = g_Htfm[b * CHN + ch];
    const float v = V_attn[ch];
    const float* fp = F + ((size_t)b * Tlen + chunk * TCH) * CHN + ch;
    float s = 0.f, ws = 0.f;
    #pragma unroll 8
    for (int t = 0; t < TCH; t++) {
        float f = fp[(size_t)t * CHN];
        float p = __expf(v * tanhfast(h + f));
        s += p;
        ws = fmaf(p, f, ws);
    }
    g_as [(b * ACH + chunk) * CHN + ch] = s;
    g_aws[(b * ACH + chunk) * CHN + ch] = ws;

    // ---- correct ordering: block-wide stores done -> fence -> ticket ----
    __syncthreads();          // all 256 threads' stores are issued
    __threadfence();          // ...and visible device-wide before we arrive
    __shared__ int is_last;
    if (ch == 0)
        is_last = (atomicAdd(&g_tick[b], 1) == ACH - 1);
    __syncthreads();
    if (is_last) {
        // all other blocks for this b arrived (each after its own fence):
        // their partials are visible. Fixed-order sum -> deterministic.
        float S = 0.f, WS = 0.f;
        #pragma unroll
        for (int c = 0; c < ACH; c++) {
            S  += g_as [(b * ACH + c) * CHN + ch];
            WS += g_aws[(b * ACH + c) * CHN + ch];
        }
        float ct = WS / S;
        d_out[OFF_CT + b * CHN + ch] = ct;
        g_At[(LAT + ch) * Bsz + b] = ct;   // A^T rows 128..383
    }
}

// ====== K4a: exp(logits) + partial softmax sums; persistent f32x2 GEMM ======
// logits = [new_h | c_t] @ [Wo ; Wct2].  Grid = 148 persistent blocks.
// 256 threads = 32 lanes (2 cols each: nq, nq+32) x 8 warps (8 b each = 4 pairs).
// A^T (96 KB) read via LDG, stays L1-resident; W streamed from DRAM (read once).
__global__ __launch_bounds__(256) void k4a_logits(const float* __restrict__ Wo,
                                                  const float* __restrict__ Wct2) {
    const int tid = threadIdx.x;
    const int nq = tid & 31;
    const int bq = tid >> 5;            // warp id; owns b in [bq*8, bq*8+8)
    const float* ab = g_At + bq * 8;    // A^T row base for this warp

    float psum[8];
    #pragma unroll
    for (int j = 0; j < 8; j++) psum[j] = 0.f;

    for (int ch = blockIdx.x; ch < NCHK; ch += GRID4) {
        const int c0 = ch * CCH + nq;   // this thread's cols: c0, c0+32
        unsigned long long acc[8];      // [pair p:4][col c:2]
        #pragma unroll
        for (int i = 0; i < 8; i++) acc[i] = 0ull;

        const float* w0p = Wo + c0;
        #pragma unroll 8
        for (int k = 0; k < LAT; k++) {
            float w0 = __ldg(w0p + (size_t)k * VOC);
            float w1 = __ldg(w0p + (size_t)k * VOC + 32);
            ulonglong2 aA = *(const ulonglong2*)(ab + k * Bsz);
            ulonglong2 aB = *(const ulonglong2*)(ab + k * Bsz + 4);
            unsigned long long wd0 = dup2(w0), wd1 = dup2(w1);
            ffma2(acc[0], aA.x, wd0); ffma2(acc[1], aA.x, wd1);
            ffma2(acc[2], aA.y, wd0); ffma2(acc[3], aA.y, wd1);
            ffma2(acc[4], aB.x, wd0); ffma2(acc[5], aB.x, wd1);
            ffma2(acc[6], aB.y, wd0); ffma2(acc[7], aB.y, wd1);
        }
        const float* w1p = Wct2 + c0;
        const float* ab2 = ab + LAT * Bsz;
        #pragma unroll 8
        for (int k = 0; k < CHN; k++) {
            float w0 = __ldg(w1p + (size_t)k * VOC);
            float w1 = __ldg(w1p + (size_t)k * VOC + 32);
            ulonglong2 aA = *(const ulonglong2*)(ab2 + k * Bsz);
            ulonglong2 aB = *(const ulonglong2*)(ab2 + k * Bsz + 4);
            unsigned long long wd0 = dup2(w0), wd1 = dup2(w1);
            ffma2(acc[0], aA.x, wd0); ffma2(acc[1], aA.x, wd1);
            ffma2(acc[2], aA.y, wd0); ffma2(acc[3], aA.y, wd1);
            ffma2(acc[4], aB.x, wd0); ffma2(acc[5], aB.x, wd1);
            ffma2(acc[6], aB.y, wd0); ffma2(acc[7], aB.y, wd1);
        }

        // epilogue: exp + store + accumulate per-b partial sums
        #pragma unroll
        for (int p = 0; p < 4; p++) {
            const int b = bq * 8 + 2 * p;
            #pragma unroll
            for (int c = 0; c < 2; c++) {
                float lo, hi;
                unpack2(acc[p * 2 + c], lo, hi);
                float e0 = __expf(lo), e1 = __expf(hi);   // logits tiny: no max needed
                const int col = c0 + 32 * c;
                g_logits[(size_t)b * VOC + col] = e0;
                g_logits[(size_t)(b + 1) * VOC + col] = e1;
                psum[2 * p]     += e0;
                psum[2 * p + 1] += e1;
            }
        }
    }

    // reduce psum across the 32 lanes of each warp
    #pragma unroll
    for (int j = 0; j < 8; j++) {
        #pragma unroll
        for (int o = 16; o > 0; o >>= 1)
            psum[j] += __shfl_xor_sync(0xffffffffu, psum[j], o);
    }
    if (nq == 0) {
        #pragma unroll
        for (int j = 0; j < 8; j++)
            g_psum[blockIdx.x * Bsz + bq * 8 + j] = psum[j];
    }
}

// ================= K4b: normalize -> O_t ================
__global__ void k4b_scale(float* __restrict__ d_out) {
    const int sl = blockIdx.x, b = blockIdx.y;   // grid (8, 64)
    const int tid = threadIdx.x;                 // 256
    __shared__ float red[256];
    red[tid] = (tid < GRID4) ? g_psum[tid * Bsz + b] : 0.f;
    __syncthreads();
    for (int s = 128; s > 0; s >>= 1) {
        if (tid < s) red[tid] += red[tid + s];
        __syncthreads();
    }
    const float inv = 1.f / red[0];
    const size_t base = (size_t)b * VOC + sl * (VOC / 8);
    for (int i = tid; i < VOC / 8; i += 256)
        d_out[OFF_O + base + i] = g_logits[base + i] * inv;
}

// ================= launch =================
extern "C" void kernel_launch(void* const* d_in, const int* in_sizes, int n_in,
                              void* d_out_v, int out_size) {
    const float* pcv       = (const float*)d_in[0];
    const float* F         = (const float*)d_in[1];
    const float* prev_char = (const float*)d_in[2];
    const float* state_h   = (const float*)d_in[3];
    const float* state_c   = (const float*)d_in[4];
    const float* Wc        = (const float*)d_in[5];
    const float* Wct1      = (const float*)d_in[6];
    const float* Wo        = (const float*)d_in[7];
    const float* Wct2      = (const float*)d_in[8];
    const float* lk        = (const float*)d_in[9];
    const float* lr        = (const float*)d_in[10];
    const float* Wh        = (const float*)d_in[11];
    const float* Va        = (const float*)d_in[12];
    float* d_out = (float*)d_out_v;

    k1_char_gemm<<<NCH1, 256>>>(prev_char, Wc);
    k2_lstm<<<Bsz, 256>>>(pcv, state_h, state_c, Wct1, lk, lr, Wh, d_out);
    k3_attn<<<dim3(ACH, Bsz), 256>>>(F, Va, d_out);
    k4a_logits<<<GRID4, 256>>>(Wo, Wct2);
    k4b_scale<<<dim3(8, Bsz), 256>>>(d_out);
}

// round 9
// speedup vs baseline: 3.0310x; 3.0310x over previous
#include <cuda_runtime.h>

#define Bsz 64
#define Tlen 1024
#define CHN 256
#define VOC 32000
#define EMB 64
#define LAT 128

// output layout (floats): O_t, c_t, new_h, new_c (tuple order, flattened)
#define OFF_O  0
#define OFF_CT (Bsz*VOC)
#define OFF_H  (OFF_CT + Bsz*CHN)
#define OFF_C  (OFF_H + Bsz*LAT)

// ---- K1: prev_char @ Wc split-K config ----
#define KC1  160
#define NCH1 (VOC / KC1)      // 200 chunks

// ---- K3: attention T-split ----
#define ACH 8
#define TCH (Tlen / ACH)      // 128

// ---- K4a: logits GEMM config (tiled, double-buffered via registers) ----
#define KTOT (LAT + CHN)      // 384
#define NT4  256              // cols per block
#define KS4  16               // k rows per staged phase
#define NPH  (KTOT / KS4)     // 24 phases
#define NBLK4 (VOC / NT4)     // 125 blocks

// -------- device scratch (static globals; no allocation) --------
__device__ float g_part1[NCH1 * Bsz * EMB];   // [chunk][b][e]
__device__ float g_Htfm[Bsz * CHN];
__device__ float g_At[KTOT * Bsz];            // A^T[k][b]: rows 0..127 new_h, 128..383 c_t
__device__ float g_as [Bsz * ACH * CHN];
__device__ float g_aws[Bsz * ACH * CHN];
__device__ float g_logits[Bsz * VOC];         // holds exp(logit) after k4a
__device__ float g_psum[NBLK4 * Bsz];         // per-(ntile,b) partial exp sums
__device__ int   g_tick[Bsz];                 // k3 completion tickets (reset by k1)

// -------- f32x2 helpers (sm_103a packed fp32) --------
__device__ __forceinline__ void ffma2(unsigned long long& acc,
                                      unsigned long long a,
                                      unsigned long long b) {
    asm("fma.rn.f32x2 %0, %1, %2, %0;" : "+l"(acc) : "l"(a), "l"(b));
}
__device__ __forceinline__ void unpack2(unsigned long long v, float& lo, float& hi) {
    asm("mov.b64 {%0, %1}, %2;" : "=f"(lo), "=f"(hi) : "l"(v));
}
__device__ __forceinline__ float tanhfast(float x) {
    float y; asm("tanh.approx.f32 %0, %1;" : "=f"(y) : "f"(x)); return y;
}

// ================= K1: partials of prev_char[64,32000] @ Wc[32000,64] =================
__global__ void k1_char_gemm(const float* __restrict__ prev_char,
                             const float* __restrict__ Wc) {
    __shared__ float Ws[KC1 * EMB];   // 40 KB
    const int chunk = blockIdx.x;
    const int k0 = chunk * KC1;
    if (threadIdx.x == 0 && chunk < Bsz) g_tick[chunk] = 0;   // reset k3 tickets
    for (int i = threadIdx.x; i < KC1 * EMB; i += 256)
        Ws[i] = Wc[k0 * EMB + i];
    __syncthreads();

    const int eq = threadIdx.x & 15;        // 16 e-groups of 4 cols
    const int bq = threadIdx.x >> 4;        // 16 b-groups of 4 rows
    const int e0 = eq * 4, b0 = bq * 4;
    float acc[4][4] = {};
    const float* a0 = prev_char + (size_t)b0 * VOC + k0;
    #pragma unroll 2
    for (int k = 0; k < KC1; k++) {
        float4 w = *(const float4*)&Ws[k * EMB + e0];
        #pragma unroll
        for (int i = 0; i < 4; i++) {
            float a = __ldg(a0 + (size_t)i * VOC + k);
            acc[i][0] = fmaf(a, w.x, acc[i][0]);
            acc[i][1] = fmaf(a, w.y, acc[i][1]);
            acc[i][2] = fmaf(a, w.z, acc[i][2]);
            acc[i][3] = fmaf(a, w.w, acc[i][3]);
        }
    }
    float* out = g_part1 + (size_t)chunk * Bsz * EMB;
    #pragma unroll
    for (int i = 0; i < 4; i++)
        #pragma unroll
        for (int j = 0; j < 4; j++)
            out[(b0 + i) * EMB + e0 + j] = acc[i][j];
}

// ================= K2: reduce partials + Wct1 term, LSTM cell, H_tfm =================
__global__ void k2_lstm(const float* __restrict__ pcv,
                        const float* __restrict__ state_h,
                        const float* __restrict__ state_c,
                        const float* __restrict__ Wct1,
                        const float* __restrict__ lstm_kernel,
                        const float* __restrict__ lstm_rec,
                        const float* __restrict__ W_h,
                        float* __restrict__ d_out) {
    const int b = blockIdx.x;
    const int tid = threadIdx.x;  // 256
    __shared__ float red_s[4][EMB];
    __shared__ float inp_s[EMB];
    __shared__ float h_s[LAT];
    __shared__ float z_s[4 * LAT];
    __shared__ float nh_s[LAT];

    const int e = tid & 63, g = tid >> 6;
    float acc = 0.f;
    for (int c = g; c < NCH1; c += 4)
        acc += g_part1[((size_t)c * Bsz + b) * EMB + e];
    for (int c = g * 64; c < g * 64 + 64; c++)
        acc = fmaf(pcv[b * CHN + c], Wct1[c * EMB + e], acc);
    red_s[g][e] = acc;
    if (tid < LAT) h_s[tid] = state_h[b * LAT + tid];
    __syncthreads();
    if (tid < EMB)
        inp_s[tid] = red_s[0][tid] + red_s[1][tid] + red_s[2][tid] + red_s[3][tid];
    __syncthreads();

    for (int j = tid; j < 4 * LAT; j += 256) {
        float z = 0.f;
        for (int ee = 0; ee < EMB; ee++)
            z = fmaf(inp_s[ee], lstm_kernel[ee * 4 * LAT + j], z);
        for (int l = 0; l < LAT; l++)
            z = fmaf(h_s[l], lstm_rec[l * 4 * LAT + j], z);
        z_s[j] = z;
    }
    __syncthreads();

    if (tid < LAT) {
        float zi = z_s[tid], zf = z_s[LAT + tid], zg = z_s[2 * LAT + tid], zo = z_s[3 * LAT + tid];
        float i_ = 1.f / (1.f + __expf(-zi));
        float f_ = 1.f / (1.f + __expf(-zf));
        float gg = tanhf(zg);
        float o_ = 1.f / (1.f + __expf(-zo));
        float nc = fmaf(f_, state_c[b * LAT + tid], i_ * gg);
        float nh = o_ * tanhf(nc);
        nh_s[tid] = nh;
        g_At[tid * Bsz + b] = nh;
        d_out[OFF_H + b * LAT + tid] = nh;
        d_out[OFF_C + b * LAT + tid] = fminf(fmaxf(nc, -10.f), 10.f);
    }
    __syncthreads();

    {
        float a2 = 0.f;
        for (int l = 0; l < LAT; l++)
            a2 = fmaf(nh_s[l], W_h[l * CHN + tid], a2);
        g_Htfm[b * CHN + tid] = a2;
    }
}

// ============ K3: attention partials + fused last-block merge -> c_t ============
// no-max softmax is safe: |e_t| <= |V_attn| (tanh bounded)
__global__ void k3_attn(const float* __restrict__ F,
                        const float* __restrict__ V_attn,
                        float* __restrict__ d_out) {
    const int chunk = blockIdx.x, b = blockIdx.y;
    const int ch = threadIdx.x;  // 256
    const float h = g_Htfm[b * CHN + ch];
    const float v = V_attn[ch];
    const float* fp = F + ((size_t)b * Tlen + chunk * TCH) * CHN + ch;
    float s = 0.f, ws = 0.f;
    #pragma unroll 8
    for (int t = 0; t < TCH; t++) {
        float f = fp[(size_t)t * CHN];
        float p = __expf(v * tanhfast(h + f));
        s += p;
        ws = fmaf(p, f, ws);
    }
    g_as [(b * ACH + chunk) * CHN + ch] = s;
    g_aws[(b * ACH + chunk) * CHN + ch] = ws;

    // block-wide stores done -> fence -> ticket
    __syncthreads();
    __threadfence();
    __shared__ int is_last;
    if (ch == 0)
        is_last = (atomicAdd(&g_tick[b], 1) == ACH - 1);
    __syncthreads();
    if (is_last) {
        float S = 0.f, WS = 0.f;
        #pragma unroll
        for (int c = 0; c < ACH; c++) {
            S  += g_as [(b * ACH + c) * CHN + ch];
            WS += g_aws[(b * ACH + c) * CHN + ch];
        }
        float ct = WS / S;
        d_out[OFF_CT + b * CHN + ch] = ct;
        g_At[(LAT + ch) * Bsz + b] = ct;   // A^T rows 128..383
    }
}

// ====== K4a: exp(logits) + partial softmax sums; smem-tiled f32x2 GEMM ======
// logits = [new_h | c_t] @ [Wo ; Wct2]. 125 blocks x 256 threads.
// Warp w owns 8 b-rows; lane nq owns cols {nq+32j, j=0..7}. acc = 32 u64 (64 regs).
// W + A tiles double-buffered through registers: prefetch kb+1 during compute kb.
__global__ __launch_bounds__(256) void k4a_logits(const float* __restrict__ Wo,
                                                  const float* __restrict__ Wct2) {
    __shared__ float2 Wd[KS4 * NT4];   // duplicated W pairs, 32 KB
    __shared__ float  As[KS4 * Bsz];   // A^T tile, 4 KB
    const int tid = threadIdx.x;
    const int nq = tid & 31;
    const int bq = tid >> 5;            // warp id; owns b in [bq*8, bq*8+8)
    const int n0 = blockIdx.x * NT4;

    unsigned long long acc[4][8];       // [b-pair][col] = 32 u64
    #pragma unroll
    for (int p = 0; p < 4; p++)
        #pragma unroll
        for (int c = 0; c < 8; c++) acc[p][c] = 0ull;

    // prefetch phase 0 into registers
    float wreg[KS4];
    float4 areg;
    {
        const float* Wsrc = Wo + n0 + tid;   // phase 0 rows 0..15 in Wo
        #pragma unroll
        for (int r = 0; r < KS4; r++)
            wreg[r] = __ldg(Wsrc + (size_t)r * VOC);
        areg = *(const float4*)&g_At[tid * 4];
    }

    for (int kb = 0; kb < NPH; kb++) {
        __syncthreads();   // previous compute done; buffers free
        #pragma unroll
        for (int r = 0; r < KS4; r++)
            Wd[r * NT4 + tid] = make_float2(wreg[r], wreg[r]);
        *(float4*)&As[tid * 4] = areg;
        __syncthreads();   // staging visible

        if (kb + 1 < NPH) {  // prefetch next phase (overlaps compute below)
            const int kg = (kb + 1) * KS4;
            const float* Wsrc = (kg < LAT)
                ? (Wo   + (size_t)kg * VOC + n0 + tid)
                : (Wct2 + (size_t)(kg - LAT) * VOC + n0 + tid);
            #pragma unroll
            for (int r = 0; r < KS4; r++)
                wreg[r] = __ldg(Wsrc + (size_t)r * VOC);
            areg = *(const float4*)&g_At[(kb + 1) * KS4 * Bsz + tid * 4];
        }

        #pragma unroll
        for (int kl = 0; kl < KS4; kl++) {
            const float* ap = As + kl * Bsz + bq * 8;
            ulonglong2 aA = *(const ulonglong2*)ap;        // broadcast within warp
            ulonglong2 aB = *(const ulonglong2*)(ap + 4);
            const float2* wrow = Wd + kl * NT4 + nq;       // lane-consecutive
            unsigned long long w[8];
            #pragma unroll
            for (int j = 0; j < 8; j++)
                w[j] = *(const unsigned long long*)(wrow + 32 * j);
            #pragma unroll
            for (int j = 0; j < 8; j++) {
                ffma2(acc[0][j], aA.x, w[j]);
                ffma2(acc[1][j], aA.y, w[j]);
                ffma2(acc[2][j], aB.x, w[j]);
                ffma2(acc[3][j], aB.y, w[j]);
            }
        }
    }

    // epilogue: exp + store + per-b partial sums
    float psum[8];
    #pragma unroll
    for (int j = 0; j < 8; j++) psum[j] = 0.f;
    #pragma unroll
    for (int p = 0; p < 4; p++) {
        const int b = bq * 8 + 2 * p;
        #pragma unroll
        for (int c = 0; c < 8; c++) {
            float lo, hi;
            unpack2(acc[p][c], lo, hi);
            float e0 = __expf(lo), e1 = __expf(hi);   // logits tiny: no max needed
            const int col = n0 + nq + 32 * c;
            g_logits[(size_t)b * VOC + col] = e0;
            g_logits[(size_t)(b + 1) * VOC + col] = e1;
            psum[2 * p]     += e0;
            psum[2 * p + 1] += e1;
        }
    }
    #pragma unroll
    for (int j = 0; j < 8; j++) {
        #pragma unroll
        for (int o = 16; o > 0; o >>= 1)
            psum[j] += __shfl_xor_sync(0xffffffffu, psum[j], o);
    }
    if (nq == 0) {
        #pragma unroll
        for (int j = 0; j < 8; j++)
            g_psum[blockIdx.x * Bsz + bq * 8 + j] = psum[j];
    }
}

// ================= K4b: normalize -> O_t ================
__global__ void k4b_scale(float* __restrict__ d_out) {
    const int sl = blockIdx.x, b = blockIdx.y;   // grid (8, 64)
    const int tid = threadIdx.x;                 // 256
    __shared__ float red[256];
    red[tid] = (tid < NBLK4) ? g_psum[tid * Bsz + b] : 0.f;
    __syncthreads();
    for (int s = 128; s > 0; s >>= 1) {
        if (tid < s) red[tid] += red[tid + s];
        __syncthreads();
    }
    const float inv = 1.f / red[0];
    const size_t base = (size_t)b * VOC + sl * (VOC / 8);
    for (int i = tid; i < VOC / 8; i += 256)
        d_out[OFF_O + base + i] = g_logits[base + i] * inv;
}

// ================= launch =================
extern "C" void kernel_launch(void* const* d_in, const int* in_sizes, int n_in,
                              void* d_out_v, int out_size) {
    const float* pcv       = (const float*)d_in[0];
    const float* F         = (const float*)d_in[1];
    const float* prev_char = (const float*)d_in[2];
    const float* state_h   = (const float*)d_in[3];
    const float* state_c   = (const float*)d_in[4];
    const float* Wc        = (const float*)d_in[5];
    const float* Wct1      = (const float*)d_in[6];
    const float* Wo        = (const float*)d_in[7];
    const float* Wct2      = (const float*)d_in[8];
    const float* lk        = (const float*)d_in[9];
    const float* lr        = (const float*)d_in[10];
    const float* Wh        = (const float*)d_in[11];
    const float* Va        = (const float*)d_in[12];
    float* d_out = (float*)d_out_v;

    k1_char_gemm<<<NCH1, 256>>>(prev_char, Wc);
    k2_lstm<<<Bsz, 256>>>(pcv, state_h, state_c, Wct1, lk, lr, Wh, d_out);
    k3_attn<<<dim3(ACH, Bsz), 256>>>(F, Va, d_out);
    k4a_logits<<<NBLK4, 256>>>(Wo, Wct2);
    k4b_scale<<<dim3(8, Bsz), 256>>>(d_out);
}

// round 11
// speedup vs baseline: 3.5180x; 1.1607x over previous
#include <cuda_runtime.h>

#define Bsz 64
#define Tlen 1024
#define CHN 256
#define VOC 32000
#define EMB 64
#define LAT 128

// output layout (floats): O_t, c_t, new_h, new_c (tuple order, flattened)
#define OFF_O  0
#define OFF_CT (Bsz*VOC)
#define OFF_H  (OFF_CT + Bsz*CHN)
#define OFF_C  (OFF_H + Bsz*LAT)

// ---- K1: prev_char @ Wc split-K config ----
#define KC1  160
#define NCH1 (VOC / KC1)      // 200 chunks

// ---- K3: attention T-split ----
#define ACH 8
#define TCH (Tlen / ACH)      // 128

// ---- K4a: logits GEMM config ----
#define KTOT (LAT + CHN)      // 384
#define NT4  256              // cols per block
#define KS4  16               // k rows per staged phase
#define NPH  (KTOT / KS4)     // 24 phases
#define NBLK4 (VOC / NT4)     // 125 blocks
#define NTH4 512              // threads per block (16 warps)

// -------- device scratch (static globals; no allocation) --------
__device__ float g_part1[NCH1 * Bsz * EMB];   // [chunk][b][e]
__device__ float g_Htfm[Bsz * CHN];
__device__ float g_At[KTOT * Bsz];            // A^T[k][b]: rows 0..127 new_h, 128..383 c_t
__device__ float g_as [Bsz * ACH * CHN];
__device__ float g_aws[Bsz * ACH * CHN];
__device__ float g_logits[Bsz * VOC];         // holds exp(logit) after k4a
__device__ float g_psum[NBLK4 * 2 * Bsz];     // per-(ntile,half,b) partial exp sums
__device__ int   g_tick[Bsz];                 // k3 completion tickets (reset by k1)

// -------- f32x2 helpers (sm_103a packed fp32) --------
__device__ __forceinline__ unsigned long long dup2(float x) {
    unsigned long long r;
    asm("mov.b64 %0, {%1, %1};" : "=l"(r) : "f"(x));
    return r;
}
__device__ __forceinline__ void ffma2(unsigned long long& acc,
                                      unsigned long long a,
                                      unsigned long long b) {
    asm("fma.rn.f32x2 %0, %1, %2, %0;" : "+l"(acc) : "l"(a), "l"(b));
}
__device__ __forceinline__ void unpack2(unsigned long long v, float& lo, float& hi) {
    asm("mov.b64 {%0, %1}, %2;" : "=f"(lo), "=f"(hi) : "l"(v));
}
__device__ __forceinline__ float tanhfast(float x) {
    float y; asm("tanh.approx.f32 %0, %1;" : "=f"(y) : "f"(x)); return y;
}

// ================= K0: null (shifts ncu capture slot to k3) =================
__global__ void k0_null() {}

// ================= K1: partials of prev_char[64,32000] @ Wc[32000,64] =================
__global__ void k1_char_gemm(const float* __restrict__ prev_char,
                             const float* __restrict__ Wc) {
    __shared__ float Ws[KC1 * EMB];   // 40 KB
    const int chunk = blockIdx.x;
    const int k0 = chunk * KC1;
    if (threadIdx.x == 0 && chunk < Bsz) g_tick[chunk] = 0;   // reset k3 tickets
    for (int i = threadIdx.x; i < KC1 * EMB; i += 256)
        Ws[i] = Wc[k0 * EMB + i];
    __syncthreads();

    const int eq = threadIdx.x & 15;        // 16 e-groups of 4 cols
    const int bq = threadIdx.x >> 4;        // 16 b-groups of 4 rows
    const int e0 = eq * 4, b0 = bq * 4;
    float acc[4][4] = {};
    const float* a0 = prev_char + (size_t)b0 * VOC + k0;
    #pragma unroll 1
    for (int k = 0; k < KC1; k += 4) {
        float4 a[4];
        #pragma unroll
        for (int i = 0; i < 4; i++)
            a[i] = *(const float4*)(a0 + (size_t)i * VOC + k);
        #pragma unroll
        for (int kk = 0; kk < 4; kk++) {
            float4 w = *(const float4*)&Ws[(k + kk) * EMB + e0];
            #pragma unroll
            for (int i = 0; i < 4; i++) {
                float av = ((const float*)&a[i])[kk];
                acc[i][0] = fmaf(av, w.x, acc[i][0]);
                acc[i][1] = fmaf(av, w.y, acc[i][1]);
                acc[i][2] = fmaf(av, w.z, acc[i][2]);
                acc[i][3] = fmaf(av, w.w, acc[i][3]);
            }
        }
    }
    float* out = g_part1 + (size_t)chunk * Bsz * EMB;
    #pragma unroll
    for (int i = 0; i < 4; i++)
        #pragma unroll
        for (int j = 0; j < 4; j++)
            out[(b0 + i) * EMB + e0 + j] = acc[i][j];
}

// ================= K2: reduce partials + Wct1 term, LSTM cell, H_tfm =================
__global__ void k2_lstm(const float* __restrict__ pcv,
                        const float* __restrict__ state_h,
                        const float* __restrict__ state_c,
                        const float* __restrict__ Wct1,
                        const float* __restrict__ lstm_kernel,
                        const float* __restrict__ lstm_rec,
                        const float* __restrict__ W_h,
                        float* __restrict__ d_out) {
    const int b = blockIdx.x;
    const int tid = threadIdx.x;  // 256
    __shared__ float red_s[4][EMB];
    __shared__ float inp_s[EMB];
    __shared__ float h_s[LAT];
    __shared__ float z_s[4 * LAT];
    __shared__ float nh_s[LAT];

    const int e = tid & 63, g = tid >> 6;
    float acc = 0.f;
    for (int c = g; c < NCH1; c += 4)
        acc += g_part1[((size_t)c * Bsz + b) * EMB + e];
    for (int c = g * 64; c < g * 64 + 64; c++)
        acc = fmaf(pcv[b * CHN + c], Wct1[c * EMB + e], acc);
    red_s[g][e] = acc;
    if (tid < LAT) h_s[tid] = state_h[b * LAT + tid];
    __syncthreads();
    if (tid < EMB)
        inp_s[tid] = red_s[0][tid] + red_s[1][tid] + red_s[2][tid] + red_s[3][tid];
    __syncthreads();

    for (int j = tid; j < 4 * LAT; j += 256) {
        float z = 0.f;
        for (int ee = 0; ee < EMB; ee++)
            z = fmaf(inp_s[ee], lstm_kernel[ee * 4 * LAT + j], z);
        for (int l = 0; l < LAT; l++)
            z = fmaf(h_s[l], lstm_rec[l * 4 * LAT + j], z);
        z_s[j] = z;
    }
    __syncthreads();

    if (tid < LAT) {
        float zi = z_s[tid], zf = z_s[LAT + tid], zg = z_s[2 * LAT + tid], zo = z_s[3 * LAT + tid];
        float i_ = 1.f / (1.f + __expf(-zi));
        float f_ = 1.f / (1.f + __expf(-zf));
        float gg = tanhf(zg);
        float o_ = 1.f / (1.f + __expf(-zo));
        float nc = fmaf(f_, state_c[b * LAT + tid], i_ * gg);
        float nh = o_ * tanhf(nc);
        nh_s[tid] = nh;
        g_At[tid * Bsz + b] = nh;
        d_out[OFF_H + b * LAT + tid] = nh;
        d_out[OFF_C + b * LAT + tid] = fminf(fmaxf(nc, -10.f), 10.f);
    }
    __syncthreads();

    {
        float a2 = 0.f;
        for (int l = 0; l < LAT; l++)
            a2 = fmaf(nh_s[l], W_h[l * CHN + tid], a2);
        g_Htfm[b * CHN + tid] = a2;
    }
}

// ============ K3: attention partials + fused last-block merge -> c_t ============
// no-max softmax is safe: |e_t| <= |V_attn| (tanh bounded)
__global__ void k3_attn(const float* __restrict__ F,
                        const float* __restrict__ V_attn,
                        float* __restrict__ d_out) {
    const int chunk = blockIdx.x, b = blockIdx.y;
    const int ch = threadIdx.x;  // 256
    const float h = g_Htfm[b * CHN + ch];
    const float v = V_attn[ch];
    const float* fp = F + ((size_t)b * Tlen + chunk * TCH) * CHN + ch;
    float s = 0.f, ws = 0.f;
    #pragma unroll 8
    for (int t = 0; t < TCH; t++) {
        float f = fp[(size_t)t * CHN];
        float p = __expf(v * tanhfast(h + f));
        s += p;
        ws = fmaf(p, f, ws);
    }
    g_as [(b * ACH + chunk) * CHN + ch] = s;
    g_aws[(b * ACH + chunk) * CHN + ch] = ws;

    // block-wide stores done -> fence -> ticket
    __syncthreads();
    __threadfence();
    __shared__ int is_last;
    if (ch == 0)
        is_last = (atomicAdd(&g_tick[b], 1) == ACH - 1);
    __syncthreads();
    if (is_last) {
        float S = 0.f, WS = 0.f;
        #pragma unroll
        for (int c = 0; c < ACH; c++) {
            S  += g_as [(b * ACH + c) * CHN + ch];
            WS += g_aws[(b * ACH + c) * CHN + ch];
        }
        float ct = WS / S;
        d_out[OFF_CT + b * CHN + ch] = ct;
        g_At[(LAT + ch) * Bsz + b] = ct;   // A^T rows 128..383
    }
}

// ====== K4a: exp(logits) + partial softmax sums; smem-tiled f32x2 GEMM ======
// logits = [new_h | c_t] @ [Wo ; Wct2]. 125 blocks x 512 threads (16 warps).
// Warp = (half: col half, bq: 8 b-rows). Lane owns 4 consecutive cols.
// W stored ONCE in smem (float); dup to f32x2 in registers (alu pipe, cheap).
// acc = 16 u64 = 32 regs. W+A double-buffered through registers.
__global__ __launch_bounds__(NTH4) void k4a_logits(const float* __restrict__ Wo,
                                                   const float* __restrict__ Wct2) {
    __shared__ float Ws[KS4 * NT4];    // 16 KB
    __shared__ float As[KS4 * Bsz];    //  4 KB
    const int tid = threadIdx.x;
    const int nq = tid & 31;
    const int w  = tid >> 5;           // warp 0..15
    const int half = w >> 3;           // col half: 0 -> cols 0..127, 1 -> 128..255
    const int bq = w & 7;              // 8 b-rows
    const int b0 = bq * 8;
    const int n0 = blockIdx.x * NT4;
    const int hi = tid >> 8;           // staging row parity
    const int wc = tid & 255;          // staging col

    unsigned long long acc[4][4];      // [b-pair][col] = 16 u64
    #pragma unroll
    for (int p = 0; p < 4; p++)
        #pragma unroll
        for (int c = 0; c < 4; c++) acc[p][c] = 0ull;

    // prefetch phase 0 into registers
    float wreg[8];
    float2 areg;
    {
        const float* Wsrc = Wo + n0 + wc;
        #pragma unroll
        for (int it = 0; it < 8; it++)
            wreg[it] = __ldg(Wsrc + (size_t)(it * 2 + hi) * VOC);
        areg = *(const float2*)&g_At[tid * 2];
    }

    for (int kb = 0; kb < NPH; kb++) {
        __syncthreads();   // previous compute done; buffers free
        #pragma unroll
        for (int it = 0; it < 8; it++)
            Ws[(it * 2 + hi) * NT4 + wc] = wreg[it];
        *(float2*)&As[tid * 2] = areg;
        __syncthreads();   // staging visible

        if (kb + 1 < NPH) {  // prefetch next phase (overlaps compute below)
            const int kg = (kb + 1) * KS4;
            const float* Wsrc = (kg < LAT)
                ? (Wo   + (size_t)kg * VOC + n0 + wc)
                : (Wct2 + (size_t)(kg - LAT) * VOC + n0 + wc);
            #pragma unroll
            for (int it = 0; it < 8; it++)
                wreg[it] = __ldg(Wsrc + (size_t)(it * 2 + hi) * VOC);
            areg = *(const float2*)&g_At[(kb + 1) * KS4 * Bsz + tid * 2];
        }

        #pragma unroll
        for (int kl = 0; kl < KS4; kl++) {
            const float* ap = As + kl * Bsz + b0;
            ulonglong2 aA = *(const ulonglong2*)ap;        // broadcast within warp
            ulonglong2 aB = *(const ulonglong2*)(ap + 4);
            float4 wv = *(const float4*)&Ws[kl * NT4 + half * 128 + nq * 4];
            unsigned long long w0 = dup2(wv.x), w1 = dup2(wv.y),
                               w2 = dup2(wv.z), w3 = dup2(wv.w);
            ffma2(acc[0][0], aA.x, w0); ffma2(acc[0][1], aA.x, w1);
            ffma2(acc[0][2], aA.x, w2); ffma2(acc[0][3], aA.x, w3);
            ffma2(acc[1][0], aA.y, w0); ffma2(acc[1][1], aA.y, w1);
            ffma2(acc[1][2], aA.y, w2); ffma2(acc[1][3], aA.y, w3);
            ffma2(acc[2][0], aB.x, w0); ffma2(acc[2][1], aB.x, w1);
            ffma2(acc[2][2], aB.x, w2); ffma2(acc[2][3], aB.x, w3);
            ffma2(acc[3][0], aB.y, w0); ffma2(acc[3][1], aB.y, w1);
            ffma2(acc[3][2], aB.y, w2); ffma2(acc[3][3], aB.y, w3);
        }
    }

    // epilogue: exp + store + per-b partial sums
    float psum[8];
    #pragma unroll
    for (int j = 0; j < 8; j++) psum[j] = 0.f;
    #pragma unroll
    for (int p = 0; p < 4; p++) {
        const int b = b0 + 2 * p;
        #pragma unroll
        for (int c = 0; c < 4; c++) {
            float lo, hiv;
            unpack2(acc[p][c], lo, hiv);
            float e0 = __expf(lo), e1 = __expf(hiv);  // logits tiny: no max needed
            const int col = n0 + half * 128 + nq * 4 + c;
            g_logits[(size_t)b * VOC + col] = e0;
            g_logits[(size_t)(b + 1) * VOC + col] = e1;
            psum[2 * p]     += e0;
            psum[2 * p + 1] += e1;
        }
    }
    #pragma unroll
    for (int j = 0; j < 8; j++) {
        #pragma unroll
        for (int o = 16; o > 0; o >>= 1)
            psum[j] += __shfl_xor_sync(0xffffffffu, psum[j], o);
    }
    if (nq == 0) {
        #pragma unroll
        for (int j = 0; j < 8; j++)
            g_psum[(blockIdx.x * 2 + half) * Bsz + b0 + j] = psum[j];
    }
}

// ================= K4b: normalize -> O_t ================
__global__ void k4b_scale(float* __restrict__ d_out) {
    const int sl = blockIdx.x, b = blockIdx.y;   // grid (8, 64)
    const int tid = threadIdx.x;                 // 256
    __shared__ float red[256];
    red[tid] = (tid < NBLK4 * 2) ? g_psum[tid * Bsz + b] : 0.f;
    __syncthreads();
    for (int s = 128; s > 0; s >>= 1) {
        if (tid < s) red[tid] += red[tid + s];
        __syncthreads();
    }
    const float inv = 1.f / red[0];
    const size_t base = (size_t)b * VOC + sl * (VOC / 8);
    for (int i = tid; i < VOC / 8; i += 256)
        d_out[OFF_O + base + i] = g_logits[base + i] * inv;
}

// ================= launch =================
extern "C" void kernel_launch(void* const* d_in, const int* in_sizes, int n_in,
                              void* d_out_v, int out_size) {
    const float* pcv       = (const float*)d_in[0];
    const float* F         = (const float*)d_in[1];
    const float* prev_char = (const float*)d_in[2];
    const float* state_h   = (const float*)d_in[3];
    const float* state_c   = (const float*)d_in[4];
    const float* Wc        = (const float*)d_in[5];
    const float* Wct1      = (const float*)d_in[6];
    const float* Wo        = (const float*)d_in[7];
    const float* Wct2      = (const float*)d_in[8];
    const float* lk        = (const float*)d_in[9];
    const float* lr        = (const float*)d_in[10];
    const float* Wh        = (const float*)d_in[11];
    const float* Va        = (const float*)d_in[12];
    float* d_out = (float*)d_out_v;

    k0_null<<<1, 32>>>();                        // idx 0: shifts ncu slot to k3
    k1_char_gemm<<<NCH1, 256>>>(prev_char, Wc);  // idx 1
    k2_lstm<<<Bsz, 256>>>(pcv, state_h, state_c, Wct1, lk, lr, Wh, d_out);  // idx 2
    k3_attn<<<dim3(ACH, Bsz), 256>>>(F, Va, d_out);   // idx 3 (profiled)
    k4a_logits<<<NBLK4, NTH4>>>(Wo, Wct2);       // idx 4
    k4b_scale<<<dim3(8, Bsz), 256>>>(d_out);     // idx 5
}

// round 12
// speedup vs baseline: 3.6821x; 1.0467x over previous
#include <cuda_runtime.h>

#define Bsz 64
#define Tlen 1024
#define CHN 256
#define VOC 32000
#define EMB 64
#define LAT 128

// output layout (floats): O_t, c_t, new_h, new_c (tuple order, flattened)
#define OFF_O  0
#define OFF_CT (Bsz*VOC)
#define OFF_H  (OFF_CT + Bsz*CHN)
#define OFF_C  (OFF_H + Bsz*LAT)

// ---- K1: prev_char @ Wc split-K config ----
#define KC1  160
#define NCH1 (VOC / KC1)      // 200 chunks

// ---- K3: attention T-split ----
#define ACH 16
#define TCH (Tlen / ACH)      // 64

// ---- K4a: logits GEMM config ----
#define KTOT (LAT + CHN)      // 384
#define NT4  256              // cols per block
#define KS4  16               // k rows per staged phase
#define NPH  (KTOT / KS4)     // 24 phases
#define NBLK4 (VOC / NT4)     // 125 blocks
#define NTH4 512              // threads per block (16 warps)

// -------- device scratch (static globals; no allocation) --------
__device__ float g_part1[NCH1 * Bsz * EMB];   // [chunk][b][e]
__device__ float g_Htfm[Bsz * CHN];
__device__ float g_At[KTOT * Bsz];            // A^T[k][b]: rows 0..127 new_h, 128..383 c_t
__device__ float g_as [Bsz * ACH * CHN];
__device__ float g_aws[Bsz * ACH * CHN];
__device__ float g_logits[Bsz * VOC];         // holds exp(logit) after k4a
__device__ float g_psum[NBLK4 * 2 * Bsz];     // per-(ntile,half,b) partial exp sums
__device__ int   g_tick[Bsz];                 // k3 completion tickets (reset by k1)

// -------- f32x2 helpers (sm_103a packed fp32) --------
__device__ __forceinline__ unsigned long long dup2(float x) {
    unsigned long long r;
    asm("mov.b64 %0, {%1, %1};" : "=l"(r) : "f"(x));
    return r;
}
__device__ __forceinline__ void ffma2(unsigned long long& acc,
                                      unsigned long long a,
                                      unsigned long long b) {
    asm("fma.rn.f32x2 %0, %1, %2, %0;" : "+l"(acc) : "l"(a), "l"(b));
}
__device__ __forceinline__ void unpack2(unsigned long long v, float& lo, float& hi) {
    asm("mov.b64 {%0, %1}, %2;" : "=f"(lo), "=f"(hi) : "l"(v));
}
__device__ __forceinline__ float tanhfast(float x) {
    float y; asm("tanh.approx.f32 %0, %1;" : "=f"(y) : "f"(x)); return y;
}

// ================= K1: partials of prev_char[64,32000] @ Wc[32000,64] =================
// f32x2: e-column pairs packed; w-pairs natural from smem, a broadcast-dup'd.
__global__ void k1_char_gemm(const float* __restrict__ prev_char,
                             const float* __restrict__ Wc) {
    __shared__ float Ws[KC1 * EMB];   // 40 KB
    const int chunk = blockIdx.x;
    const int k0 = chunk * KC1;
    if (threadIdx.x == 0 && chunk < Bsz) g_tick[chunk] = 0;   // reset k3 tickets
    for (int i = threadIdx.x; i < KC1 * EMB; i += 256)
        Ws[i] = Wc[k0 * EMB + i];
    __syncthreads();

    const int eq = threadIdx.x & 15;        // 16 e-groups of 4 cols
    const int bq = threadIdx.x >> 4;        // 16 b-groups of 4 rows
    const int e0 = eq * 4, b0 = bq * 4;
    unsigned long long acc[4][2];           // [b][e-pair]
    #pragma unroll
    for (int i = 0; i < 4; i++) { acc[i][0] = 0ull; acc[i][1] = 0ull; }

    const float* a0 = prev_char + (size_t)b0 * VOC + k0;
    #pragma unroll 1
    for (int k = 0; k < KC1; k += 4) {
        float4 a[4];
        #pragma unroll
        for (int i = 0; i < 4; i++)
            a[i] = *(const float4*)(a0 + (size_t)i * VOC + k);
        #pragma unroll
        for (int kk = 0; kk < 4; kk++) {
            unsigned long long w01 = *(const unsigned long long*)&Ws[(k + kk) * EMB + e0];
            unsigned long long w23 = *(const unsigned long long*)&Ws[(k + kk) * EMB + e0 + 2];
            #pragma unroll
            for (int i = 0; i < 4; i++) {
                unsigned long long av = dup2(((const float*)&a[i])[kk]);
                ffma2(acc[i][0], av, w01);
                ffma2(acc[i][1], av, w23);
            }
        }
    }
    float* out = g_part1 + (size_t)chunk * Bsz * EMB;
    #pragma unroll
    for (int i = 0; i < 4; i++) {
        float v0, v1, v2, v3;
        unpack2(acc[i][0], v0, v1);
        unpack2(acc[i][1], v2, v3);
        float* o = out + (b0 + i) * EMB + e0;
        o[0] = v0; o[1] = v1; o[2] = v2; o[3] = v3;
    }
}

// ================= K2: reduce partials + Wct1 term, LSTM cell, H_tfm =================
__global__ void k2_lstm(const float* __restrict__ pcv,
                        const float* __restrict__ state_h,
                        const float* __restrict__ state_c,
                        const float* __restrict__ Wct1,
                        const float* __restrict__ lstm_kernel,
                        const float* __restrict__ lstm_rec,
                        const float* __restrict__ W_h,
                        float* __restrict__ d_out) {
    const int b = blockIdx.x;
    const int tid = threadIdx.x;  // 256
    __shared__ float red_s[4][EMB];
    __shared__ float inp_s[EMB];
    __shared__ float h_s[LAT];
    __shared__ float z_s[4 * LAT];
    __shared__ float nh_s[LAT];

    const int e = tid & 63, g = tid >> 6;
    float acc = 0.f;
    for (int c = g; c < NCH1; c += 4)
        acc += g_part1[((size_t)c * Bsz + b) * EMB + e];
    for (int c = g * 64; c < g * 64 + 64; c++)
        acc = fmaf(pcv[b * CHN + c], Wct1[c * EMB + e], acc);
    red_s[g][e] = acc;
    if (tid < LAT) h_s[tid] = state_h[b * LAT + tid];
    __syncthreads();
    if (tid < EMB)
        inp_s[tid] = red_s[0][tid] + red_s[1][tid] + red_s[2][tid] + red_s[3][tid];
    __syncthreads();

    for (int j = tid; j < 4 * LAT; j += 256) {
        float z = 0.f;
        for (int ee = 0; ee < EMB; ee++)
            z = fmaf(inp_s[ee], lstm_kernel[ee * 4 * LAT + j], z);
        for (int l = 0; l < LAT; l++)
            z = fmaf(h_s[l], lstm_rec[l * 4 * LAT + j], z);
        z_s[j] = z;
    }
    __syncthreads();

    if (tid < LAT) {
        float zi = z_s[tid], zf = z_s[LAT + tid], zg = z_s[2 * LAT + tid], zo = z_s[3 * LAT + tid];
        float i_ = 1.f / (1.f + __expf(-zi));
        float f_ = 1.f / (1.f + __expf(-zf));
        float gg = tanhf(zg);
        float o_ = 1.f / (1.f + __expf(-zo));
        float nc = fmaf(f_, state_c[b * LAT + tid], i_ * gg);
        float nh = o_ * tanhf(nc);
        nh_s[tid] = nh;
        g_At[tid * Bsz + b] = nh;
        d_out[OFF_H + b * LAT + tid] = nh;
        d_out[OFF_C + b * LAT + tid] = fminf(fmaxf(nc, -10.f), 10.f);
    }
    __syncthreads();

    {
        float a2 = 0.f;
        for (int l = 0; l < LAT; l++)
            a2 = fmaf(nh_s[l], W_h[l * CHN + tid], a2);
        g_Htfm[b * CHN + tid] = a2;
    }
}

// ============ K3: attention partials + fused last-block merge -> c_t ============
// no-max softmax is safe: |e_t| <= |V_attn| (tanh bounded)
__global__ void k3_attn(const float* __restrict__ F,
                        const float* __restrict__ V_attn,
                        float* __restrict__ d_out) {
    const int chunk = blockIdx.x, b = blockIdx.y;
    const int ch = threadIdx.x;  // 256
    const float h = g_Htfm[b * CHN + ch];
    const float v = V_attn[ch];
    const float* fp = F + ((size_t)b * Tlen + chunk * TCH) * CHN + ch;
    float s = 0.f, ws = 0.f;
    #pragma unroll 8
    for (int t = 0; t < TCH; t++) {
        float f = fp[(size_t)t * CHN];
        float p = __expf(v * tanhfast(h + f));
        s += p;
        ws = fmaf(p, f, ws);
    }
    g_as [(b * ACH + chunk) * CHN + ch] = s;
    g_aws[(b * ACH + chunk) * CHN + ch] = ws;

    // block-wide stores done -> fence -> ticket
    __syncthreads();
    __threadfence();
    __shared__ int is_last;
    if (ch == 0)
        is_last = (atomicAdd(&g_tick[b], 1) == ACH - 1);
    __syncthreads();
    if (is_last) {
        float S = 0.f, WS = 0.f;
        #pragma unroll
        for (int c = 0; c < ACH; c++) {
            S  += g_as [(b * ACH + c) * CHN + ch];
            WS += g_aws[(b * ACH + c) * CHN + ch];
        }
        float ct = WS / S;
        d_out[OFF_CT + b * CHN + ch] = ct;
        g_At[(LAT + ch) * Bsz + b] = ct;   // A^T rows 128..383
    }
}

// ====== K4a: exp(logits) + partial softmax sums; smem-tiled f32x2 GEMM ======
// logits = [new_h | c_t] @ [Wo ; Wct2]. 125 blocks x 512 threads (16 warps).
// Warp = (half: col half, bq: 8 b-rows). Lane owns 4 consecutive cols.
// W stored ONCE in smem (float); dup to f32x2 in registers (alu pipe, cheap).
// acc = 16 u64 = 32 regs. W+A double-buffered through registers.
__global__ __launch_bounds__(NTH4) void k4a_logits(const float* __restrict__ Wo,
                                                   const float* __restrict__ Wct2) {
    __shared__ float Ws[KS4 * NT4];    // 16 KB
    __shared__ float As[KS4 * Bsz];    //  4 KB
    const int tid = threadIdx.x;
    const int nq = tid & 31;
    const int w  = tid >> 5;           // warp 0..15
    const int half = w >> 3;           // col half: 0 -> cols 0..127, 1 -> 128..255
    const int bq = w & 7;              // 8 b-rows
    const int b0 = bq * 8;
    const int n0 = blockIdx.x * NT4;
    const int hi = tid >> 8;           // staging row parity
    const int wc = tid & 255;          // staging col

    unsigned long long acc[4][4];      // [b-pair][col] = 16 u64
    #pragma unroll
    for (int p = 0; p < 4; p++)
        #pragma unroll
        for (int c = 0; c < 4; c++) acc[p][c] = 0ull;

    // prefetch phase 0 into registers
    float wreg[8];
    float2 areg;
    {
        const float* Wsrc = Wo + n0 + wc;
        #pragma unroll
        for (int it = 0; it < 8; it++)
            wreg[it] = __ldg(Wsrc + (size_t)(it * 2 + hi) * VOC);
        areg = *(const float2*)&g_At[tid * 2];
    }

    for (int kb = 0; kb < NPH; kb++) {
        __syncthreads();   // previous compute done; buffers free
        #pragma unroll
        for (int it = 0; it < 8; it++)
            Ws[(it * 2 + hi) * NT4 + wc] = wreg[it];
        *(float2*)&As[tid * 2] = areg;
        __syncthreads();   // staging visible

        if (kb + 1 < NPH) {  // prefetch next phase (overlaps compute below)
            const int kg = (kb + 1) * KS4;
            const float* Wsrc = (kg < LAT)
                ? (Wo   + (size_t)kg * VOC + n0 + wc)
                : (Wct2 + (size_t)(kg - LAT) * VOC + n0 + wc);
            #pragma unroll
            for (int it = 0; it < 8; it++)
                wreg[it] = __ldg(Wsrc + (size_t)(it * 2 + hi) * VOC);
            areg = *(const float2*)&g_At[(kb + 1) * KS4 * Bsz + tid * 2];
        }

        #pragma unroll
        for (int kl = 0; kl < KS4; kl++) {
            const float* ap = As + kl * Bsz + b0;
            ulonglong2 aA = *(const ulonglong2*)ap;        // broadcast within warp
            ulonglong2 aB = *(const ulonglong2*)(ap + 4);
            float4 wv = *(const float4*)&Ws[kl * NT4 + half * 128 + nq * 4];
            unsigned long long w0 = dup2(wv.x), w1 = dup2(wv.y),
                               w2 = dup2(wv.z), w3 = dup2(wv.w);
            ffma2(acc[0][0], aA.x, w0); ffma2(acc[0][1], aA.x, w1);
            ffma2(acc[0][2], aA.x, w2); ffma2(acc[0][3], aA.x, w3);
            ffma2(acc[1][0], aA.y, w0); ffma2(acc[1][1], aA.y, w1);
            ffma2(acc[1][2], aA.y, w2); ffma2(acc[1][3], aA.y, w3);
            ffma2(acc[2][0], aB.x, w0); ffma2(acc[2][1], aB.x, w1);
            ffma2(acc[2][2], aB.x, w2); ffma2(acc[2][3], aB.x, w3);
            ffma2(acc[3][0], aB.y, w0); ffma2(acc[3][1], aB.y, w1);
            ffma2(acc[3][2], aB.y, w2); ffma2(acc[3][3], aB.y, w3);
        }
    }

    // epilogue: exp + store + per-b partial sums
    float psum[8];
    #pragma unroll
    for (int j = 0; j < 8; j++) psum[j] = 0.f;
    #pragma unroll
    for (int p = 0; p < 4; p++) {
        const int b = b0 + 2 * p;
        #pragma unroll
        for (int c = 0; c < 4; c++) {
            float lo, hiv;
            unpack2(acc[p][c], lo, hiv);
            float e0 = __expf(lo), e1 = __expf(hiv);  // logits tiny: no max needed
            const int col = n0 + half * 128 + nq * 4 + c;
            g_logits[(size_t)b * VOC + col] = e0;
            g_logits[(size_t)(b + 1) * VOC + col] = e1;
            psum[2 * p]     += e0;
            psum[2 * p + 1] += e1;
        }
    }
    #pragma unroll
    for (int j = 0; j < 8; j++) {
        #pragma unroll
        for (int o = 16; o > 0; o >>= 1)
            psum[j] += __shfl_xor_sync(0xffffffffu, psum[j], o);
    }
    if (nq == 0) {
        #pragma unroll
        for (int j = 0; j < 8; j++)
            g_psum[(blockIdx.x * 2 + half) * Bsz + b0 + j] = psum[j];
    }
}

// ================= K4b: normalize -> O_t ================
__global__ void k4b_scale(float* __restrict__ d_out) {
    const int sl = blockIdx.x, b = blockIdx.y;   // grid (8, 64)
    const int tid = threadIdx.x;                 // 256
    __shared__ float red[256];
    red[tid] = (tid < NBLK4 * 2) ? g_psum[tid * Bsz + b] : 0.f;
    __syncthreads();
    for (int s = 128; s > 0; s >>= 1) {
        if (tid < s) red[tid] += red[tid + s];
        __syncthreads();
    }
    const float inv = 1.f / red[0];
    const size_t base = (size_t)b * VOC + sl * (VOC / 8);
    for (int i = tid; i < VOC / 8; i += 256)
        d_out[OFF_O + base + i] = g_logits[base + i] * inv;
}

// ================= launch =================
extern "C" void kernel_launch(void* const* d_in, const int* in_sizes, int n_in,
                              void* d_out_v, int out_size) {
    const float* pcv       = (const float*)d_in[0];
    const float* F         = (const float*)d_in[1];
    const float* prev_char = (const float*)d_in[2];
    const float* state_h   = (const float*)d_in[3];
    const float* state_c   = (const float*)d_in[4];
    const float* Wc        = (const float*)d_in[5];
    const float* Wct1      = (const float*)d_in[6];
    const float* Wo        = (const float*)d_in[7];
    const float* Wct2      = (const float*)d_in[8];
    const float* lk        = (const float*)d_in[9];
    const float* lr        = (const float*)d_in[10];
    const float* Wh        = (const float*)d_in[11];
    const float* Va        = (const float*)d_in[12];
    float* d_out = (float*)d_out_v;

    k1_char_gemm<<<NCH1, 256>>>(prev_char, Wc);                              // idx 0
    k2_lstm<<<Bsz, 256>>>(pcv, state_h, state_c, Wct1, lk, lr, Wh, d_out);   // idx 1
    k3_attn<<<dim3(ACH, Bsz), 256>>>(F, Va, d_out);                          // idx 2
    k4a_logits<<<NBLK4, NTH4>>>(Wo, Wct2);                                   // idx 3 (profiled)
    k4b_scale<<<dim3(8, Bsz), 256>>>(d_out);                                 // idx 4
}